// round 16
// baseline (speedup 1.0000x reference)
#include <cuda_runtime.h>
#include <cuda_bf16.h>
#include <math.h>
#include <stdint.h>

// Problem constants
#define B_ 2
#define T_ 2048
#define C_ 2048
#define H_ 16
#define KVH_ 4
#define D_ 128
#define M_ (B_ * T_)          // 4096
#define KVC_ (KVH_ * D_)      // 512
#define SCALE_ 0.08838834764831845f
#define RMS_EPS 1.1920929e-07f

// ---------------------------------------------------------------------------
// Scratch (device globals; no allocation allowed)
// ---------------------------------------------------------------------------
__device__ float g_q[(size_t)M_ * C_];
__device__ float g_k[(size_t)M_ * KVC_];
__device__ float g_v[(size_t)M_ * KVC_];
__device__ float g_y[(size_t)M_ * C_];
__device__ float g_x[(size_t)M_ * C_];
__device__ float g_wq[(size_t)C_ * C_];    // transposed [n][k]
__device__ float g_wk[(size_t)C_ * KVC_];  // transposed [n][k]
__device__ float g_wv[(size_t)C_ * KVC_];  // transposed [n][k]
__device__ float g_wo[(size_t)C_ * C_];    // transposed [n][k]

// ---------------------------------------------------------------------------
// helpers
// ---------------------------------------------------------------------------
__device__ __forceinline__ uint32_t smem_u32(const void* p) {
    uint32_t a;
    asm("{ .reg .u64 t; cvta.to.shared.u64 t, %1; cvt.u32.u64 %0, t; }" : "=r"(a) : "l"(p));
    return a;
}

__device__ __forceinline__ float tf32r(float x) {
    unsigned u;
    asm("cvt.rna.tf32.f32 %0, %1;" : "=r"(u) : "f"(x));
    return __uint_as_float(u);
}

__device__ __forceinline__ void cp16(uint32_t s, const void* g) {
    asm volatile("cp.async.cg.shared.global [%0], [%1], 16;" :: "r"(s), "l"(g) : "memory");
}
#define CP_COMMIT() asm volatile("cp.async.commit_group;" ::: "memory")
#define CP_WAIT(n)  asm volatile("cp.async.wait_group %0;" :: "n"(n) : "memory")

__device__ __forceinline__ void mma_tf32(float* c, const float* a, const float* b) {
    const unsigned* A = reinterpret_cast<const unsigned*>(a);
    const unsigned* Bv = reinterpret_cast<const unsigned*>(b);
    asm volatile(
        "mma.sync.aligned.m16n8k8.row.col.f32.tf32.tf32.f32 "
        "{%0,%1,%2,%3}, {%4,%5,%6,%7}, {%8,%9}, {%0,%1,%2,%3};\n"
        : "+f"(c[0]), "+f"(c[1]), "+f"(c[2]), "+f"(c[3])
        : "r"(A[0]), "r"(A[1]), "r"(A[2]), "r"(A[3]), "r"(Bv[0]), "r"(Bv[1]));
}

// ldmatrix x4 / x2: 8x8 b16 tiles == 8x4 tf32 tiles.
__device__ __forceinline__ void ldsm4(uint32_t* r, uint32_t addr) {
    asm volatile("ldmatrix.sync.aligned.m8n8.x4.shared.b16 {%0,%1,%2,%3}, [%4];"
        : "=r"(r[0]), "=r"(r[1]), "=r"(r[2]), "=r"(r[3]) : "r"(addr));
}
__device__ __forceinline__ void ldsm2(uint32_t* r, uint32_t addr) {
    asm volatile("ldmatrix.sync.aligned.m8n8.x2.shared.b16 {%0,%1}, [%2];"
        : "=r"(r[0]), "=r"(r[1]) : "r"(addr));
}

// ---------------------------------------------------------------------------
// tf32 pre-round kernel (elementwise, for x)
// ---------------------------------------------------------------------------
__global__ __launch_bounds__(256) void tf32_round_kernel(
    const float4* __restrict__ src, float4* __restrict__ dst, int n4)
{
    int i = blockIdx.x * 256 + threadIdx.x;
    if (i < n4) {
        float4 v = src[i];
        dst[i] = make_float4(tf32r(v.x), tf32r(v.y), tf32r(v.z), tf32r(v.w));
    }
}

// tf32 round + transpose: dst[n][k] = tf32(src[k][n]). 32x32 tiles, 256 thr.
__global__ __launch_bounds__(256) void tf32_round_T_kernel(
    const float* __restrict__ src, float* __restrict__ dst, int K, int N)
{
    __shared__ float t[32][33];
    const int n0 = blockIdx.x * 32;
    const int k0 = blockIdx.y * 32;
    const int tx = threadIdx.x & 31;
    const int ty = threadIdx.x >> 5;
    #pragma unroll
    for (int i = 0; i < 32; i += 8)
        t[ty + i][tx] = src[(size_t)(k0 + ty + i) * N + n0 + tx];
    __syncthreads();
    #pragma unroll
    for (int i = 0; i < 32; i += 8)
        dst[(size_t)(n0 + ty + i) * K + k0 + tx] = tf32r(t[tx][ty + i]);
}

// ---------------------------------------------------------------------------
// cp.async 3-stage pipelined tf32 GEMM mainloop with ldmatrix fragment loads.
// (unchanged from R14/R15)
// ---------------------------------------------------------------------------
#define A_ST 36
#define TBUF (128 * A_ST)
#define STAGES 3
#define GEMM_SM_FLOATS (STAGES * 2 * TBUF)      // 110592 B
#define STAGE_ST 132

__device__ __forceinline__ void gemm_main(
    const float* __restrict__ Ab, const float* __restrict__ Bt,
    int K, float* sm, float acc[4][4][4])
{
    const uint32_t sA = smem_u32(sm);
    const uint32_t sB = sA + (uint32_t)STAGES * TBUF * 4;

    const int tid = threadIdx.x;
    const int lane = tid & 31;
    const int wid = tid >> 5;
    const int wy = wid & 1;
    const int wx = wid >> 1;

    #pragma unroll
    for (int i = 0; i < 4; i++)
        #pragma unroll
        for (int j = 0; j < 4; j++)
            #pragma unroll
            for (int r = 0; r < 4; r++) acc[i][j][r] = 0.f;

    const int NT = K >> 5;

    const int laneA = ((lane & 8) + (lane & 7)) * A_ST + (lane >> 4) * 4;
    const int laneB = (((lane >> 4) << 3) + (lane & 7)) * A_ST + ((lane >> 3) & 1) * 4;

    auto load_stage = [&](int t, int slot) {
        const float* An = Ab + t * 32;
        const float* Bn = Bt + t * 32;
        #pragma unroll
        for (int i = 0; i < 4; i++) {
            int idx = tid + i * 256;
            int r = idx >> 3, cg = (idx & 7) << 2;
            cp16(sA + (uint32_t)(slot * TBUF + r * A_ST + cg) * 4,
                 An + (size_t)r * K + cg);
        }
        #pragma unroll
        for (int i = 0; i < 4; i++) {
            int idx = tid + i * 256;
            int r = idx >> 3, cg = (idx & 7) << 2;
            cp16(sB + (uint32_t)(slot * TBUF + r * A_ST + cg) * 4,
                 Bn + (size_t)r * K + cg);
        }
    };

    #pragma unroll
    for (int s = 0; s < STAGES - 1; s++) {
        if (s < NT) load_stage(s, s);
        CP_COMMIT();
    }

    int slot = 0;
    for (int t = 0; t < NT; t++) {
        CP_WAIT(STAGES - 2);
        __syncthreads();

        int u = t + STAGES - 1;
        int uslot = slot + STAGES - 1;
        if (uslot >= STAGES) uslot -= STAGES;
        if (u < NT) load_stage(u, uslot);
        CP_COMMIT();

        const uint32_t aS = sA + (uint32_t)(slot * TBUF) * 4;
        const uint32_t bS = sB + (uint32_t)(slot * TBUF) * 4;
        #pragma unroll
        for (int ks = 0; ks < 32; ks += 8) {
            uint32_t af[4][4], bf[2][4];
            #pragma unroll
            for (int mi = 0; mi < 4; mi++)
                ldsm4(af[mi], aS + (uint32_t)((wy * 64 + mi * 16) * A_ST + ks + laneA) * 4);
            #pragma unroll
            for (int p = 0; p < 2; p++)
                ldsm4(bf[p], bS + (uint32_t)((wx * 32 + p * 16) * A_ST + ks + laneB) * 4);
            #pragma unroll
            for (int mi = 0; mi < 4; mi++)
                #pragma unroll
                for (int ni = 0; ni < 4; ni++)
                    mma_tf32(acc[mi][ni], (float*)af[mi],
                             (float*)(&bf[ni >> 1][(ni & 1) * 2]));
        }
        if (++slot == STAGES) slot = 0;
    }
}

// Plain epilogue
template <bool ROUND>
__device__ __forceinline__ void epi_plain(float acc[4][4][4], float* out, int Nout)
{
    const int tid = threadIdx.x;
    const int lane = tid & 31;
    const int wid = tid >> 5;
    const int t4 = lane >> 2;
    const int tm4 = lane & 3;
    const int wy = wid & 1;
    const int wx = wid >> 1;
    #pragma unroll
    for (int mi = 0; mi < 4; mi++) {
        int row = wy * 64 + mi * 16 + t4;
        #pragma unroll
        for (int ni = 0; ni < 4; ni++) {
            int col = wx * 32 + ni * 8 + tm4 * 2;
            float a0 = acc[mi][ni][0], a1 = acc[mi][ni][1];
            float a2 = acc[mi][ni][2], a3 = acc[mi][ni][3];
            if (ROUND) { a0 = tf32r(a0); a1 = tf32r(a1); a2 = tf32r(a2); a3 = tf32r(a3); }
            *(float2*)(out + (size_t)row * Nout + col) = make_float2(a0, a1);
            *(float2*)(out + (size_t)(row + 8) * Nout + col) = make_float2(a2, a3);
        }
    }
}

// RoPE + RMSNorm epilogue (stores tf32-rounded)
__device__ __forceinline__ void epi_rope(
    float acc[4][4][4], float* sm,
    const float* __restrict__ cs, const float* __restrict__ sn,
    float* out, int Nout, int m0)
{
    float* stage = sm;
    const int tid = threadIdx.x;
    const int lane = tid & 31;
    const int wid = tid >> 5;
    const int t4 = lane >> 2;
    const int tm4 = lane & 3;
    const int wy = wid & 1;
    const int wx = wid >> 1;

    __syncthreads();
    #pragma unroll
    for (int mi = 0; mi < 4; mi++) {
        int row = wy * 64 + mi * 16 + t4;
        #pragma unroll
        for (int ni = 0; ni < 4; ni++) {
            int col = wx * 32 + ni * 8 + tm4 * 2;
            *(float2*)(&stage[row * STAGE_ST + col]) = make_float2(acc[mi][ni][0], acc[mi][ni][1]);
            *(float2*)(&stage[(row + 8) * STAGE_ST + col]) = make_float2(acc[mi][ni][2], acc[mi][ni][3]);
        }
    }
    __syncthreads();

    {
        const int r = tid >> 1;
        const int hf = tid & 1;
        const int tpos = (m0 + r) & (T_ - 1);
        const float* cr = cs + tpos * 64;
        const float* sr = sn + tpos * 64;
        float* row = &stage[r * STAGE_ST];

        float ss = 0.f;
        #pragma unroll 8
        for (int j = 0; j < 64; j++) {
            float x1 = row[j], x2 = row[j + 64];
            float c = cr[j], s = sr[j];
            float val = hf ? (x2 * c - x1 * s) : (x1 * c + x2 * s);
            ss += val * val;
        }
        ss += __shfl_xor_sync(0xffffffffu, ss, 1);
        float inv = rsqrtf(ss * (1.f / 128.f) + RMS_EPS);

        #pragma unroll 8
        for (int j = 0; j < 64; j++) {
            float x1 = row[j], x2 = row[j + 64];
            float c = cr[j], s = sr[j];
            float val = hf ? (x2 * c - x1 * s) : (x1 * c + x2 * s);
            row[hf * 64 + j] = tf32r(val * inv);
        }
    }
    __syncthreads();

    {
        const int c4 = lane * 4;
        const int rb = tid >> 5;
        #pragma unroll
        for (int p = 0; p < 16; p++) {
            int row = p * 8 + rb;
            float4 v = *(const float4*)(&stage[row * STAGE_ST + c4]);
            *(float4*)(out + (size_t)row * Nout + c4) = v;
        }
    }
}

// ---------------------------------------------------------------------------
// Fused QKV projection + RoPE + RMSNorm. grid (24, 32), 256 threads, 2 CTA/SM.
// ---------------------------------------------------------------------------
__global__ __launch_bounds__(256, 2) void gemm_qkv(
    const float* __restrict__ x,
    const float* __restrict__ WqT, const float* __restrict__ WkT, const float* __restrict__ WvT,
    const float* __restrict__ cs, const float* __restrict__ sn,
    float* __restrict__ q, float* __restrict__ k, float* __restrict__ v)
{
    extern __shared__ float sm[];
    const int bx = blockIdx.x;
    const int m0 = blockIdx.y * 128;

    const float* Bt;
    float* outp;
    int Nb, colt;
    bool dorope;
    if (bx < 16)      { Bt = WqT; outp = q; Nb = C_;   colt = bx * 128;        dorope = true; }
    else if (bx < 20) { Bt = WkT; outp = k; Nb = KVC_; colt = (bx - 16) * 128; dorope = true; }
    else              { Bt = WvT; outp = v; Nb = KVC_; colt = (bx - 20) * 128; dorope = false; }

    float acc[4][4][4];
    gemm_main(x + (size_t)m0 * C_, Bt + (size_t)colt * C_, C_, sm, acc);

    float* out_tile = outp + (size_t)m0 * Nb + colt;
    if (dorope) epi_rope(acc, sm, cs, sn, out_tile, Nb, m0);
    else        epi_plain<true>(acc, out_tile, Nb);
}

// ---------------------------------------------------------------------------
// Output projection: out = y @ Wo (WoT pre-transposed). grid (16, 32).
// ---------------------------------------------------------------------------
__global__ __launch_bounds__(256, 2) void gemm_out(
    const float* __restrict__ y, const float* __restrict__ WoT, float* __restrict__ out)
{
    extern __shared__ float sm[];
    const int m0 = blockIdx.y * 128;
    const int colt = blockIdx.x * 128;
    float acc[4][4][4];
    gemm_main(y + (size_t)m0 * C_, WoT + (size_t)colt * C_, C_, sm, acc);
    epi_plain<false>(acc, out + (size_t)m0 * C_ + colt, C_);
}

// ---------------------------------------------------------------------------
// Flash attention (causal, GQA rep=4), tf32 mma + ldmatrix.
// Br=64, Bc=32, 256 threads (8 warps 2x4), smem 112384 B -> 2 CTAs/SM.
// S warp tile 32x8 (ldsm2 B-frags), PV warp tile 32x32.
// K/V double-buffered via cp.async.
// ---------------------------------------------------------------------------
#define FA_BR 64
#define FA_BC 32
#define Q_ST 132
#define K_ST 132
#define V_ST 136
#define S_ST 36

#define SM_Q   0
#define SM_K   (FA_BR * Q_ST)                    // 8448
#define SM_V   (SM_K + 2 * FA_BC * K_ST)         // 16896
#define SM_S   (SM_V + 2 * FA_BC * V_ST)         // 25600
#define SM_M   (SM_S + FA_BR * S_ST)             // 27904
#define SM_L   (SM_M + FA_BR)
#define SM_A   (SM_L + FA_BR)
#define FA_SMEM_FLOATS (SM_A + FA_BR)            // 28096 floats = 112384 B

__global__ __launch_bounds__(256, 2) void flash_attn_tf32(
    const float* __restrict__ q, const float* __restrict__ k,
    const float* __restrict__ v, float* __restrict__ y)
{
    extern __shared__ float sm[];
    float* Vs = sm + SM_V;
    float* Ss = sm + SM_S;
    float* m_s = sm + SM_M;
    float* l_s = sm + SM_L;
    float* a_s = sm + SM_A;
    const uint32_t sbase = smem_u32(sm);

    const int tid = threadIdx.x;
    const int lane = tid & 31;
    const int wid = tid >> 5;
    const int t4 = lane >> 2;
    const int tm4 = lane & 3;
    const int wy = wid & 1;
    const int wx = wid >> 1;

    const int bh = blockIdx.y;
    const int b = bh >> 4;
    const int h = bh & 15;
    const int kvh = h >> 2;
    const int qt = gridDim.x - 1 - blockIdx.x;   // reversed: long CTAs first
    const int q0 = qt * FA_BR;
    const int L = 2 * qt + 1;                    // last k-tile (Bc=32)

    const float* qbase = q + (size_t)b * T_ * C_ + h * D_;
    const float* kbase = k + (size_t)b * T_ * KVC_ + kvh * D_;
    const float* vbase = v + (size_t)b * T_ * KVC_ + kvh * D_;

    // ldmatrix lane offsets (floats)
    const int lrow = (lane & 8) + (lane & 7);
    const int lcol = (lane >> 4) * 4;
    const int laneA_Q = lrow * Q_ST + lcol;
    const int laneA_S = lrow * S_ST + lcol;
    const int laneB2_K = (lane & 7) * K_ST + ((lane >> 3) & 1) * 4;  // x2 B-frag

    auto issue_kv = [&](int kt, int slot) {
        const float* kb = kbase + (size_t)(kt * FA_BC) * KVC_;
        const float* vb = vbase + (size_t)(kt * FA_BC) * KVC_;
        #pragma unroll
        for (int i = 0; i < 4; i++) {
            int idx = tid + i * 256;
            int r = idx >> 5;
            int c = (idx & 31) << 2;
            cp16(sbase + (uint32_t)(SM_K + slot * FA_BC * K_ST + r * K_ST + c) * 4,
                 kb + (size_t)r * KVC_ + c);
            cp16(sbase + (uint32_t)(SM_V + slot * FA_BC * V_ST + r * V_ST + c) * 4,
                 vb + (size_t)r * KVC_ + c);
        }
    };

    // Prologue: Q + KV(0)
    #pragma unroll
    for (int i = 0; i < 8; i++) {
        int idx = tid + i * 256;
        int r = idx >> 5;
        int c = (idx & 31) << 2;
        cp16(sbase + (uint32_t)(SM_Q + r * Q_ST + c) * 4,
             qbase + (size_t)(q0 + r) * C_ + c);
    }
    issue_kv(0, 0);
    CP_COMMIT();

    if (tid < FA_BR) { m_s[tid] = -INFINITY; l_s[tid] = 0.f; }

    float o[2][4][4];
    #pragma unroll
    for (int i = 0; i < 2; i++)
        #pragma unroll
        for (int j = 0; j < 4; j++)
            #pragma unroll
            for (int r = 0; r < 4; r++) o[i][j][r] = 0.f;

    for (int kt = 0; kt <= L; kt++) {
        const int slot = kt & 1;
        CP_WAIT(0);
        __syncthreads();

        if (kt < L) { issue_kv(kt + 1, slot ^ 1); CP_COMMIT(); }

        const uint32_t qS = sbase + (uint32_t)SM_Q * 4;
        const uint32_t kS = sbase + (uint32_t)(SM_K + slot * FA_BC * K_ST) * 4;
        float* Vsb = Vs + slot * FA_BC * V_ST;

        // S = Q @ K^T  (warp tile 32x8)
        float sacc[2][4];
        #pragma unroll
        for (int i = 0; i < 2; i++)
            #pragma unroll
            for (int r = 0; r < 4; r++) sacc[i][r] = 0.f;

        #pragma unroll
        for (int ks = 0; ks < D_; ks += 8) {
            uint32_t af[2][4], bf[2];
            #pragma unroll
            for (int mi = 0; mi < 2; mi++)
                ldsm4(af[mi], qS + (uint32_t)((wy * 32 + mi * 16) * Q_ST + ks + laneA_Q) * 4);
            ldsm2(bf, kS + (uint32_t)((wx * 8) * K_ST + ks + laneB2_K) * 4);
            #pragma unroll
            for (int mi = 0; mi < 2; mi++)
                mma_tf32(sacc[mi], (float*)af[mi], (float*)bf);
        }

        // Scale + causal mask + store S
        const bool diag = (kt >= 2 * qt);
        const int coff = kt * FA_BC - q0;
        #pragma unroll
        for (int mi = 0; mi < 2; mi++) {
            int rA = wy * 32 + mi * 16 + t4;
            int cA = wx * 8 + tm4 * 2;
            #pragma unroll
            for (int half = 0; half < 2; half++) {
                int r = rA + half * 8;
                float v0 = sacc[mi][half * 2 + 0] * SCALE_;
                float v1 = sacc[mi][half * 2 + 1] * SCALE_;
                if (diag) {
                    if (coff + cA > r) v0 = -INFINITY;
                    if (coff + cA + 1 > r) v1 = -INFINITY;
                }
                *(float2*)(&Ss[r * S_ST + cA]) = make_float2(v0, v1);
            }
        }
        __syncthreads();

        // Online softmax: 4 threads per row, 8 cols each
        {
            const int srow = tid >> 2;
            const int ssub = tid & 3;
            float* Srow = Ss + srow * S_ST + ssub * 8;
            float mo = m_s[srow];
            float mx = mo;
            #pragma unroll
            for (int j = 0; j < 8; j++) mx = fmaxf(mx, Srow[j]);
            mx = fmaxf(mx, __shfl_xor_sync(0xffffffffu, mx, 1));
            mx = fmaxf(mx, __shfl_xor_sync(0xffffffffu, mx, 2));
            float sum = 0.f;
            #pragma unroll
            for (int j = 0; j < 8; j++) {
                float p = __expf(Srow[j] - mx);
                Srow[j] = tf32r(p);
                sum += p;
            }
            sum += __shfl_xor_sync(0xffffffffu, sum, 1);
            sum += __shfl_xor_sync(0xffffffffu, sum, 2);
            if (ssub == 0) {
                float alpha = __expf(mo - mx);
                a_s[srow] = alpha;
                l_s[srow] = l_s[srow] * alpha + sum;
                m_s[srow] = mx;
            }
        }
        __syncthreads();

        // Rescale + PV (warp tile 32x32 over k=32)
        #pragma unroll
        for (int mi = 0; mi < 2; mi++) {
            int rb = wy * 32 + mi * 16 + t4;
            float al0 = a_s[rb];
            float al1 = a_s[rb + 8];
            #pragma unroll
            for (int ni = 0; ni < 4; ni++) {
                o[mi][ni][0] *= al0; o[mi][ni][1] *= al0;
                o[mi][ni][2] *= al1; o[mi][ni][3] *= al1;
            }
        }

        const uint32_t sS = sbase + (uint32_t)SM_S * 4;
        #pragma unroll
        for (int ks = 0; ks < FA_BC; ks += 8) {
            uint32_t af[2][4];
            float bfr[4][2];
            #pragma unroll
            for (int mi = 0; mi < 2; mi++)
                ldsm4(af[mi], sS + (uint32_t)((wy * 32 + mi * 16) * S_ST + ks + laneA_S) * 4);
            #pragma unroll
            for (int ni = 0; ni < 4; ni++) {
                int cb = wx * 32 + ni * 8;
                bfr[ni][0] = Vsb[(ks + tm4) * V_ST + cb + t4];
                bfr[ni][1] = Vsb[(ks + tm4 + 4) * V_ST + cb + t4];
            }
            #pragma unroll
            for (int mi = 0; mi < 2; mi++)
                #pragma unroll
                for (int ni = 0; ni < 4; ni++)
                    mma_tf32(o[mi][ni], (float*)af[mi], bfr[ni]);
        }
    }

    __syncthreads();
    // Epilogue: divide by l, write y (tf32-rounded for gemm_out)
    float* ybase = y + (size_t)b * T_ * C_ + h * D_;
    #pragma unroll
    for (int mi = 0; mi < 2; mi++) {
        int rb = wy * 32 + mi * 16 + t4;
        float inv0 = 1.f / l_s[rb];
        float inv1 = 1.f / l_s[rb + 8];
        #pragma unroll
        for (int ni = 0; ni < 4; ni++) {
            int col = wx * 32 + ni * 8 + tm4 * 2;
            float* d0 = ybase + (size_t)(q0 + rb) * C_ + col;
            float* d1 = ybase + (size_t)(q0 + rb + 8) * C_ + col;
            *(float2*)d0 = make_float2(tf32r(o[mi][ni][0] * inv0), tf32r(o[mi][ni][1] * inv0));
            *(float2*)d1 = make_float2(tf32r(o[mi][ni][2] * inv1), tf32r(o[mi][ni][3] * inv1));
        }
    }
}

// ---------------------------------------------------------------------------
// Launch
// ---------------------------------------------------------------------------
extern "C" void kernel_launch(void* const* d_in, const int* in_sizes, int n_in,
                              void* d_out, int out_size)
{
    const float* x   = (const float*)d_in[0];
    const float* cs  = (const float*)d_in[1];
    const float* sn  = (const float*)d_in[2];
    const float* Wq  = (const float*)d_in[3];
    const float* Wk  = (const float*)d_in[4];
    const float* Wv  = (const float*)d_in[5];
    const float* Wo  = (const float*)d_in[6];
    float* out = (float*)d_out;

    float *qp, *kp, *vp, *yp, *xp, *wqp, *wkp, *wvp, *wop;
    cudaGetSymbolAddress((void**)&qp, g_q);
    cudaGetSymbolAddress((void**)&kp, g_k);
    cudaGetSymbolAddress((void**)&vp, g_v);
    cudaGetSymbolAddress((void**)&yp, g_y);
    cudaGetSymbolAddress((void**)&xp, g_x);
    cudaGetSymbolAddress((void**)&wqp, g_wq);
    cudaGetSymbolAddress((void**)&wkp, g_wk);
    cudaGetSymbolAddress((void**)&wvp, g_wv);
    cudaGetSymbolAddress((void**)&wop, g_wo);

    const int gemm_smem = GEMM_SM_FLOATS * 4;   // 110592 B -> 2 CTA/SM
    cudaFuncSetAttribute(gemm_qkv, cudaFuncAttributeMaxDynamicSharedMemorySize, gemm_smem);
    cudaFuncSetAttribute(gemm_out, cudaFuncAttributeMaxDynamicSharedMemorySize, gemm_smem);
    const int fa_smem = FA_SMEM_FLOATS * 4;     // 112384 B -> 2 CTA/SM
    cudaFuncSetAttribute(flash_attn_tf32, cudaFuncAttributeMaxDynamicSharedMemorySize, fa_smem);

    dim3 blk256(256);
    {
        int n4 = (M_ * C_) / 4;
        tf32_round_kernel<<<(n4 + 255) / 256, blk256>>>((const float4*)x, (float4*)xp, n4);
        tf32_round_T_kernel<<<dim3(C_ / 32, C_ / 32), blk256>>>(Wq, wqp, C_, C_);
        tf32_round_T_kernel<<<dim3(KVC_ / 32, C_ / 32), blk256>>>(Wk, wkp, C_, KVC_);
        tf32_round_T_kernel<<<dim3(KVC_ / 32, C_ / 32), blk256>>>(Wv, wvp, C_, KVC_);
        tf32_round_T_kernel<<<dim3(C_ / 32, C_ / 32), blk256>>>(Wo, wop, C_, C_);
    }
    gemm_qkv<<<dim3(24, M_ / 128), blk256, gemm_smem>>>(xp, wqp, wkp, wvp, cs, sn, qp, kp, vp);
    flash_attn_tf32<<<dim3(T_ / FA_BR, B_ * H_), blk256, fa_smem>>>(qp, kp, vp, yp);
    gemm_out<<<dim3(C_ / 128, M_ / 128), blk256, gemm_smem>>>(yp, wop, out);
}

// round 17
// speedup vs baseline: 1.1061x; 1.1061x over previous
#include <cuda_runtime.h>
#include <cuda_bf16.h>
#include <math.h>
#include <stdint.h>

// Problem constants
#define B_ 2
#define T_ 2048
#define C_ 2048
#define H_ 16
#define KVH_ 4
#define D_ 128
#define M_ (B_ * T_)          // 4096
#define KVC_ (KVH_ * D_)      // 512
#define SCALE_ 0.08838834764831845f
#define RMS_EPS 1.1920929e-07f

// ---------------------------------------------------------------------------
// Scratch (device globals; no allocation allowed)
// ---------------------------------------------------------------------------
__device__ float g_q[(size_t)M_ * C_];
__device__ float g_k[(size_t)M_ * KVC_];
__device__ float g_v[(size_t)M_ * KVC_];   // holds V TRANSPOSED: [kvh][b][d][t]
__device__ float g_y[(size_t)M_ * C_];
__device__ float g_x[(size_t)M_ * C_];
__device__ float g_wq[(size_t)C_ * C_];    // transposed [n][k]
__device__ float g_wk[(size_t)C_ * KVC_];  // transposed [n][k]
__device__ float g_wv[(size_t)C_ * KVC_];  // transposed [n][k]
__device__ float g_wo[(size_t)C_ * C_];    // transposed [n][k]

// ---------------------------------------------------------------------------
// helpers
// ---------------------------------------------------------------------------
__device__ __forceinline__ uint32_t smem_u32(const void* p) {
    uint32_t a;
    asm("{ .reg .u64 t; cvta.to.shared.u64 t, %1; cvt.u32.u64 %0, t; }" : "=r"(a) : "l"(p));
    return a;
}

__device__ __forceinline__ float tf32r(float x) {
    unsigned u;
    asm("cvt.rna.tf32.f32 %0, %1;" : "=r"(u) : "f"(x));
    return __uint_as_float(u);
}

__device__ __forceinline__ void cp16(uint32_t s, const void* g) {
    asm volatile("cp.async.cg.shared.global [%0], [%1], 16;" :: "r"(s), "l"(g) : "memory");
}
#define CP_COMMIT() asm volatile("cp.async.commit_group;" ::: "memory")
#define CP_WAIT(n)  asm volatile("cp.async.wait_group %0;" :: "n"(n) : "memory")

__device__ __forceinline__ void mma_tf32(float* c, const float* a, const float* b) {
    const unsigned* A = reinterpret_cast<const unsigned*>(a);
    const unsigned* Bv = reinterpret_cast<const unsigned*>(b);
    asm volatile(
        "mma.sync.aligned.m16n8k8.row.col.f32.tf32.tf32.f32 "
        "{%0,%1,%2,%3}, {%4,%5,%6,%7}, {%8,%9}, {%0,%1,%2,%3};\n"
        : "+f"(c[0]), "+f"(c[1]), "+f"(c[2]), "+f"(c[3])
        : "r"(A[0]), "r"(A[1]), "r"(A[2]), "r"(A[3]), "r"(Bv[0]), "r"(Bv[1]));
}

__device__ __forceinline__ void ldsm4(uint32_t* r, uint32_t addr) {
    asm volatile("ldmatrix.sync.aligned.m8n8.x4.shared.b16 {%0,%1,%2,%3}, [%4];"
        : "=r"(r[0]), "=r"(r[1]), "=r"(r[2]), "=r"(r[3]) : "r"(addr));
}

// ---------------------------------------------------------------------------
// tf32 pre-round kernels
// ---------------------------------------------------------------------------
__global__ __launch_bounds__(256) void tf32_round_kernel(
    const float4* __restrict__ src, float4* __restrict__ dst, int n4)
{
    int i = blockIdx.x * 256 + threadIdx.x;
    if (i < n4) {
        float4 v = src[i];
        dst[i] = make_float4(tf32r(v.x), tf32r(v.y), tf32r(v.z), tf32r(v.w));
    }
}

__global__ __launch_bounds__(256) void tf32_round_T_kernel(
    const float* __restrict__ src, float* __restrict__ dst, int K, int N)
{
    __shared__ float t[32][33];
    const int n0 = blockIdx.x * 32;
    const int k0 = blockIdx.y * 32;
    const int tx = threadIdx.x & 31;
    const int ty = threadIdx.x >> 5;
    #pragma unroll
    for (int i = 0; i < 32; i += 8)
        t[ty + i][tx] = src[(size_t)(k0 + ty + i) * N + n0 + tx];
    __syncthreads();
    #pragma unroll
    for (int i = 0; i < 32; i += 8)
        dst[(size_t)(n0 + ty + i) * K + k0 + tx] = tf32r(t[tx][ty + i]);
}

// ---------------------------------------------------------------------------
// cp.async 3-stage pipelined tf32 GEMM mainloop (unchanged from R15)
// ---------------------------------------------------------------------------
#define A_ST 36
#define TBUF (128 * A_ST)
#define STAGES 3
#define GEMM_SM_FLOATS (STAGES * 2 * TBUF)      // 110592 B
#define STAGE_ST 132

__device__ __forceinline__ void gemm_main(
    const float* __restrict__ Ab, const float* __restrict__ Bt,
    int K, float* sm, float acc[4][4][4])
{
    const uint32_t sA = smem_u32(sm);
    const uint32_t sB = sA + (uint32_t)STAGES * TBUF * 4;

    const int tid = threadIdx.x;
    const int lane = tid & 31;
    const int wid = tid >> 5;
    const int wy = wid & 1;
    const int wx = wid >> 1;

    #pragma unroll
    for (int i = 0; i < 4; i++)
        #pragma unroll
        for (int j = 0; j < 4; j++)
            #pragma unroll
            for (int r = 0; r < 4; r++) acc[i][j][r] = 0.f;

    const int NT = K >> 5;

    const int laneA = ((lane & 8) + (lane & 7)) * A_ST + (lane >> 4) * 4;
    const int laneB = (((lane >> 4) << 3) + (lane & 7)) * A_ST + ((lane >> 3) & 1) * 4;

    auto load_stage = [&](int t, int slot) {
        const float* An = Ab + t * 32;
        const float* Bn = Bt + t * 32;
        #pragma unroll
        for (int i = 0; i < 4; i++) {
            int idx = tid + i * 256;
            int r = idx >> 3, cg = (idx & 7) << 2;
            cp16(sA + (uint32_t)(slot * TBUF + r * A_ST + cg) * 4,
                 An + (size_t)r * K + cg);
        }
        #pragma unroll
        for (int i = 0; i < 4; i++) {
            int idx = tid + i * 256;
            int r = idx >> 3, cg = (idx & 7) << 2;
            cp16(sB + (uint32_t)(slot * TBUF + r * A_ST + cg) * 4,
                 Bn + (size_t)r * K + cg);
        }
    };

    #pragma unroll
    for (int s = 0; s < STAGES - 1; s++) {
        if (s < NT) load_stage(s, s);
        CP_COMMIT();
    }

    int slot = 0;
    for (int t = 0; t < NT; t++) {
        CP_WAIT(STAGES - 2);
        __syncthreads();

        int u = t + STAGES - 1;
        int uslot = slot + STAGES - 1;
        if (uslot >= STAGES) uslot -= STAGES;
        if (u < NT) load_stage(u, uslot);
        CP_COMMIT();

        const uint32_t aS = sA + (uint32_t)(slot * TBUF) * 4;
        const uint32_t bS = sB + (uint32_t)(slot * TBUF) * 4;
        #pragma unroll
        for (int ks = 0; ks < 32; ks += 8) {
            uint32_t af[4][4], bf[2][4];
            #pragma unroll
            for (int mi = 0; mi < 4; mi++)
                ldsm4(af[mi], aS + (uint32_t)((wy * 64 + mi * 16) * A_ST + ks + laneA) * 4);
            #pragma unroll
            for (int p = 0; p < 2; p++)
                ldsm4(bf[p], bS + (uint32_t)((wx * 32 + p * 16) * A_ST + ks + laneB) * 4);
            #pragma unroll
            for (int mi = 0; mi < 4; mi++)
                #pragma unroll
                for (int ni = 0; ni < 4; ni++)
                    mma_tf32(acc[mi][ni], (float*)af[mi],
                             (float*)(&bf[ni >> 1][(ni & 1) * 2]));
        }
        if (++slot == STAGES) slot = 0;
    }
}

// Plain epilogue
template <bool ROUND>
__device__ __forceinline__ void epi_plain(float acc[4][4][4], float* out, int Nout)
{
    const int tid = threadIdx.x;
    const int lane = tid & 31;
    const int wid = tid >> 5;
    const int t4 = lane >> 2;
    const int tm4 = lane & 3;
    const int wy = wid & 1;
    const int wx = wid >> 1;
    #pragma unroll
    for (int mi = 0; mi < 4; mi++) {
        int row = wy * 64 + mi * 16 + t4;
        #pragma unroll
        for (int ni = 0; ni < 4; ni++) {
            int col = wx * 32 + ni * 8 + tm4 * 2;
            float a0 = acc[mi][ni][0], a1 = acc[mi][ni][1];
            float a2 = acc[mi][ni][2], a3 = acc[mi][ni][3];
            if (ROUND) { a0 = tf32r(a0); a1 = tf32r(a1); a2 = tf32r(a2); a3 = tf32r(a3); }
            *(float2*)(out + (size_t)row * Nout + col) = make_float2(a0, a1);
            *(float2*)(out + (size_t)(row + 8) * Nout + col) = make_float2(a2, a3);
        }
    }
}

// Transposed V epilogue: stage tile (tf32-rounded), write dst[d][t] rows.
// dst points to the head's [d][t] plane (row stride T_), t0 = row offset.
__device__ __forceinline__ void epi_plain_T(
    float acc[4][4][4], float* sm, float* dst, int t0)
{
    float* stage = sm;
    const int tid = threadIdx.x;
    const int lane = tid & 31;
    const int wid = tid >> 5;
    const int t4 = lane >> 2;
    const int tm4 = lane & 3;
    const int wy = wid & 1;
    const int wx = wid >> 1;

    __syncthreads();
    #pragma unroll
    for (int mi = 0; mi < 4; mi++) {
        int row = wy * 64 + mi * 16 + t4;
        #pragma unroll
        for (int ni = 0; ni < 4; ni++) {
            int col = wx * 32 + ni * 8 + tm4 * 2;
            stage[row * STAGE_ST + col]     = tf32r(acc[mi][ni][0]);
            stage[row * STAGE_ST + col + 1] = tf32r(acc[mi][ni][1]);
            stage[(row + 8) * STAGE_ST + col]     = tf32r(acc[mi][ni][2]);
            stage[(row + 8) * STAGE_ST + col + 1] = tf32r(acc[mi][ni][3]);
        }
    }
    __syncthreads();

    // warp handles d-rows wid, wid+8, ... (16 rows); coalesced writes along t
    #pragma unroll
    for (int g = 0; g < 16; g++) {
        int d = wid + 8 * g;
        float* drow = dst + (size_t)d * T_ + t0;
        #pragma unroll
        for (int i = 0; i < 4; i++)
            drow[lane + 32 * i] = stage[(lane + 32 * i) * STAGE_ST + d];
    }
}

// ---------------------------------------------------------------------------
// Fused QKV projection + RoPE + RMSNorm. grid (24, 32), 256 threads, 2 CTA/SM.
// V written TRANSPOSED into vT layout [kvh][b][d][t].
// ---------------------------------------------------------------------------
__device__ __forceinline__ void epi_rope(
    float acc[4][4][4], float* sm,
    const float* __restrict__ cs, const float* __restrict__ sn,
    float* out, int Nout, int m0)
{
    float* stage = sm;
    const int tid = threadIdx.x;
    const int lane = tid & 31;
    const int wid = tid >> 5;
    const int t4 = lane >> 2;
    const int tm4 = lane & 3;
    const int wy = wid & 1;
    const int wx = wid >> 1;

    __syncthreads();
    #pragma unroll
    for (int mi = 0; mi < 4; mi++) {
        int row = wy * 64 + mi * 16 + t4;
        #pragma unroll
        for (int ni = 0; ni < 4; ni++) {
            int col = wx * 32 + ni * 8 + tm4 * 2;
            *(float2*)(&stage[row * STAGE_ST + col]) = make_float2(acc[mi][ni][0], acc[mi][ni][1]);
            *(float2*)(&stage[(row + 8) * STAGE_ST + col]) = make_float2(acc[mi][ni][2], acc[mi][ni][3]);
        }
    }
    __syncthreads();

    {
        const int r = tid >> 1;
        const int hf = tid & 1;
        const int tpos = (m0 + r) & (T_ - 1);
        const float* cr = cs + tpos * 64;
        const float* sr = sn + tpos * 64;
        float* row = &stage[r * STAGE_ST];

        float ss = 0.f;
        #pragma unroll 8
        for (int j = 0; j < 64; j++) {
            float x1 = row[j], x2 = row[j + 64];
            float c = cr[j], s = sr[j];
            float val = hf ? (x2 * c - x1 * s) : (x1 * c + x2 * s);
            ss += val * val;
        }
        ss += __shfl_xor_sync(0xffffffffu, ss, 1);
        float inv = rsqrtf(ss * (1.f / 128.f) + RMS_EPS);

        #pragma unroll 8
        for (int j = 0; j < 64; j++) {
            float x1 = row[j], x2 = row[j + 64];
            float c = cr[j], s = sr[j];
            float val = hf ? (x2 * c - x1 * s) : (x1 * c + x2 * s);
            row[hf * 64 + j] = tf32r(val * inv);
        }
    }
    __syncthreads();

    {
        const int c4 = lane * 4;
        const int rb = tid >> 5;
        #pragma unroll
        for (int p = 0; p < 16; p++) {
            int row = p * 8 + rb;
            float4 v = *(const float4*)(&stage[row * STAGE_ST + c4]);
            *(float4*)(out + (size_t)row * Nout + c4) = v;
        }
    }
}

__global__ __launch_bounds__(256, 2) void gemm_qkv(
    const float* __restrict__ x,
    const float* __restrict__ WqT, const float* __restrict__ WkT, const float* __restrict__ WvT,
    const float* __restrict__ cs, const float* __restrict__ sn,
    float* __restrict__ q, float* __restrict__ k, float* __restrict__ vT)
{
    extern __shared__ float sm[];
    const int bx = blockIdx.x;
    const int m0 = blockIdx.y * 128;

    if (bx < 20) {
        const float* Bt;
        float* outp;
        int Nb, colt;
        if (bx < 16) { Bt = WqT; outp = q; Nb = C_;   colt = bx * 128; }
        else         { Bt = WkT; outp = k; Nb = KVC_; colt = (bx - 16) * 128; }
        float acc[4][4][4];
        gemm_main(x + (size_t)m0 * C_, Bt + (size_t)colt * C_, C_, sm, acc);
        epi_rope(acc, sm, cs, sn, outp + (size_t)m0 * Nb + colt, Nb, m0);
    } else {
        const int kvh = bx - 20;
        float acc[4][4][4];
        gemm_main(x + (size_t)m0 * C_, WvT + (size_t)(kvh * 128) * C_, C_, sm, acc);
        const int b = m0 / T_;
        const int t0 = m0 % T_;
        float* dst = vT + (size_t)(kvh * B_ + b) * D_ * T_;
        epi_plain_T(acc, sm, dst, t0);
    }
}

__global__ __launch_bounds__(256, 2) void gemm_out(
    const float* __restrict__ y, const float* __restrict__ WoT, float* __restrict__ out)
{
    extern __shared__ float sm[];
    const int m0 = blockIdx.y * 128;
    const int colt = blockIdx.x * 128;
    float acc[4][4][4];
    gemm_main(y + (size_t)m0 * C_, WoT + (size_t)colt * C_, C_, sm, acc);
    epi_plain<false>(acc, out + (size_t)m0 * C_ + colt, C_);
}

// ---------------------------------------------------------------------------
// Flash attention, FA2-style register softmax.
// Br=128, Bc=64, 256 threads (8 warps), warp w owns rows 16w..16w+15 x all 64 cols.
// One barrier per iteration (KV buffer flip). No S tile in smem.
// V in smem transposed [d][key] -> PV B-frags via ldmatrix.
// ---------------------------------------------------------------------------
#define FA_BR 128
#define FA_BC 64
#define Q_ST 132
#define K_ST 132
#define VT_ST 68

#define SM_Q   0
#define SM_K   (FA_BR * Q_ST)                    // 16896
#define SM_V   (SM_K + 2 * FA_BC * K_ST)         // 33792
#define FA_SMEM_FLOATS (SM_V + 2 * D_ * VT_ST)   // 51200 floats = 204800 B

__global__ __launch_bounds__(256, 1) void flash_attn_tf32(
    const float* __restrict__ q, const float* __restrict__ k,
    const float* __restrict__ vT, float* __restrict__ y)
{
    extern __shared__ float sm[];
    const uint32_t sbase = smem_u32(sm);

    const int tid = threadIdx.x;
    const int lane = tid & 31;
    const int wid = tid >> 5;
    const int t4 = lane >> 2;
    const int tm4 = lane & 3;

    const int bh = blockIdx.y;
    const int b = bh >> 4;
    const int h = bh & 15;
    const int kvh = h >> 2;
    const int qt = gridDim.x - 1 - blockIdx.x;   // reversed: long CTAs first
    const int q0 = qt * FA_BR;
    const int L = 2 * qt + 1;

    const float* qbase = q + (size_t)b * T_ * C_ + h * D_;
    const float* kbase = k + (size_t)b * T_ * KVC_ + kvh * D_;
    const float* vtb = vT + (size_t)(kvh * B_ + b) * D_ * T_;

    // ldmatrix lane offsets (floats)
    const int lrow = (lane & 8) + (lane & 7);
    const int lcol = (lane >> 4) * 4;
    const int laneA_Q = lrow * Q_ST + lcol;
    const int brow = ((lane >> 4) << 3) + (lane & 7);
    const int bcol = ((lane >> 3) & 1) * 4;
    const int laneB_K = brow * K_ST + bcol;
    const int laneB_V = brow * VT_ST + bcol;

    auto issue_kv = [&](int kt, int slot) {
        const float* kb = kbase + (size_t)(kt * FA_BC) * KVC_;
        #pragma unroll
        for (int i = 0; i < 8; i++) {
            int idx = tid + i * 256;
            int kr = idx >> 5, kc = (idx & 31) << 2;
            cp16(sbase + (uint32_t)(SM_K + slot * FA_BC * K_ST + kr * K_ST + kc) * 4,
                 kb + (size_t)kr * KVC_ + kc);
            int vr = idx >> 4, vc = (idx & 15) << 2;
            cp16(sbase + (uint32_t)(SM_V + slot * D_ * VT_ST + vr * VT_ST + vc) * 4,
                 vtb + (size_t)vr * T_ + kt * FA_BC + vc);
        }
    };

    // Prologue: Q (128x128) + KV(0)
    #pragma unroll
    for (int i = 0; i < 16; i++) {
        int idx = tid + i * 256;
        int r = idx >> 5, c = (idx & 31) << 2;
        cp16(sbase + (uint32_t)(SM_Q + r * Q_ST + c) * 4,
             qbase + (size_t)(q0 + r) * C_ + c);
    }
    issue_kv(0, 0);
    CP_COMMIT();

    float o[16][4];
    #pragma unroll
    for (int i = 0; i < 16; i++)
        #pragma unroll
        for (int r = 0; r < 4; r++) o[i][r] = 0.f;
    float m0 = -INFINITY, m1 = -INFINITY, l0 = 0.f, l1 = 0.f;

    const int r0 = wid * 16 + t4;    // local row (row+8 = r1)
    const int srcA = (lane & ~3) | (tm4 >> 1);
    const int srcB = srcA + 2;

    for (int kt = 0; kt <= L; kt++) {
        const int slot = kt & 1;
        CP_WAIT(0);
        __syncthreads();

        if (kt < L) { issue_kv(kt + 1, slot ^ 1); CP_COMMIT(); }

        const uint32_t qS = sbase + (uint32_t)SM_Q * 4;
        const uint32_t kS = sbase + (uint32_t)(SM_K + slot * FA_BC * K_ST) * 4;
        const uint32_t vS = sbase + (uint32_t)(SM_V + slot * D_ * VT_ST) * 4;

        // S = Q @ K^T : warp tile 16 x 64
        float sacc[8][4];
        #pragma unroll
        for (int i = 0; i < 8; i++)
            #pragma unroll
            for (int r = 0; r < 4; r++) sacc[i][r] = 0.f;

        #pragma unroll
        for (int ks = 0; ks < D_; ks += 8) {
            uint32_t aq[4], kb[4][4];
            ldsm4(aq, qS + (uint32_t)((wid * 16) * Q_ST + ks + laneA_Q) * 4);
            #pragma unroll
            for (int p = 0; p < 4; p++)
                ldsm4(kb[p], kS + (uint32_t)((p * 16) * K_ST + ks + laneB_K) * 4);
            #pragma unroll
            for (int ni = 0; ni < 8; ni++)
                mma_tf32(sacc[ni], (float*)aq, (float*)(&kb[ni >> 1][(ni & 1) * 2]));
        }

        // Scale + causal mask (register domain)
        const bool diag = (kt >= 2 * qt);
        const int coff = kt * FA_BC - q0;
        #pragma unroll
        for (int ni = 0; ni < 8; ni++) {
            int c0 = coff + 8 * ni + 2 * tm4;
            float s0 = sacc[ni][0] * SCALE_;
            float s1 = sacc[ni][1] * SCALE_;
            float s2 = sacc[ni][2] * SCALE_;
            float s3 = sacc[ni][3] * SCALE_;
            if (diag) {
                if (c0 > r0) s0 = -INFINITY;
                if (c0 + 1 > r0) s1 = -INFINITY;
                if (c0 > r0 + 8) s2 = -INFINITY;
                if (c0 + 1 > r0 + 8) s3 = -INFINITY;
            }
            sacc[ni][0] = s0; sacc[ni][1] = s1; sacc[ni][2] = s2; sacc[ni][3] = s3;
        }

        // Row max via quad reduce
        float mx0 = -INFINITY, mx1 = -INFINITY;
        #pragma unroll
        for (int ni = 0; ni < 8; ni++) {
            mx0 = fmaxf(mx0, fmaxf(sacc[ni][0], sacc[ni][1]));
            mx1 = fmaxf(mx1, fmaxf(sacc[ni][2], sacc[ni][3]));
        }
        mx0 = fmaxf(mx0, __shfl_xor_sync(0xffffffffu, mx0, 1));
        mx0 = fmaxf(mx0, __shfl_xor_sync(0xffffffffu, mx0, 2));
        mx1 = fmaxf(mx1, __shfl_xor_sync(0xffffffffu, mx1, 1));
        mx1 = fmaxf(mx1, __shfl_xor_sync(0xffffffffu, mx1, 2));

        float mn0 = fmaxf(m0, mx0), mn1 = fmaxf(m1, mx1);
        float a0 = __expf(m0 - mn0), a1 = __expf(m1 - mn1);

        // P = exp(S - m), tf32-rounded; row sums via quad reduce
        float sum0 = 0.f, sum1 = 0.f;
        #pragma unroll
        for (int ni = 0; ni < 8; ni++) {
            float p0 = __expf(sacc[ni][0] - mn0);
            float p1 = __expf(sacc[ni][1] - mn0);
            float p2 = __expf(sacc[ni][2] - mn1);
            float p3 = __expf(sacc[ni][3] - mn1);
            sum0 += p0 + p1;
            sum1 += p2 + p3;
            sacc[ni][0] = tf32r(p0); sacc[ni][1] = tf32r(p1);
            sacc[ni][2] = tf32r(p2); sacc[ni][3] = tf32r(p3);
        }
        sum0 += __shfl_xor_sync(0xffffffffu, sum0, 1);
        sum0 += __shfl_xor_sync(0xffffffffu, sum0, 2);
        sum1 += __shfl_xor_sync(0xffffffffu, sum1, 1);
        sum1 += __shfl_xor_sync(0xffffffffu, sum1, 2);
        l0 = l0 * a0 + sum0;
        l1 = l1 * a1 + sum1;
        m0 = mn0; m1 = mn1;

        // Rescale O
        #pragma unroll
        for (int ni = 0; ni < 16; ni++) {
            o[ni][0] *= a0; o[ni][1] *= a0;
            o[ni][2] *= a1; o[ni][3] *= a1;
        }

        // O += P @ V : per k-block j, permute P C-frag -> A-frag, ldsm V B-frags
        #pragma unroll
        for (int j = 0; j < 8; j++) {
            float e0 = __shfl_sync(0xffffffffu, sacc[j][0], srcA);
            float e1 = __shfl_sync(0xffffffffu, sacc[j][1], srcA);
            float e2 = __shfl_sync(0xffffffffu, sacc[j][2], srcA);
            float e3 = __shfl_sync(0xffffffffu, sacc[j][3], srcA);
            float f0 = __shfl_sync(0xffffffffu, sacc[j][0], srcB);
            float f1 = __shfl_sync(0xffffffffu, sacc[j][1], srcB);
            float f2 = __shfl_sync(0xffffffffu, sacc[j][2], srcB);
            float f3 = __shfl_sync(0xffffffffu, sacc[j][3], srcB);
            float pa[4];
            pa[0] = (tm4 & 1) ? e1 : e0;   // (t4,      tm4)
            pa[1] = (tm4 & 1) ? e3 : e2;   // (t4+8,    tm4)
            pa[2] = (tm4 & 1) ? f1 : f0;   // (t4,    tm4+4)
            pa[3] = (tm4 & 1) ? f3 : f2;   // (t4+8,  tm4+4)

            uint32_t vb[8][4];
            #pragma unroll
            for (int p = 0; p < 8; p++)
                ldsm4(vb[p], vS + (uint32_t)((p * 16) * VT_ST + j * 8 + laneB_V) * 4);
            #pragma unroll
            for (int ni = 0; ni < 16; ni++)
                mma_tf32(o[ni], pa, (float*)(&vb[ni >> 1][(ni & 1) * 2]));
        }
    }

    // Epilogue: divide by l, write y (tf32-rounded for gemm_out)
    float inv0 = 1.f / l0, inv1 = 1.f / l1;
    float* ybase = y + (size_t)b * T_ * C_ + h * D_;
    const int gr0 = q0 + r0;
    #pragma unroll
    for (int ni = 0; ni < 16; ni++) {
        int col = 8 * ni + 2 * tm4;
        *(float2*)(ybase + (size_t)gr0 * C_ + col) =
            make_float2(tf32r(o[ni][0] * inv0), tf32r(o[ni][1] * inv0));
        *(float2*)(ybase + (size_t)(gr0 + 8) * C_ + col) =
            make_float2(tf32r(o[ni][2] * inv1), tf32r(o[ni][3] * inv1));
    }
}

// ---------------------------------------------------------------------------
// Launch
// ---------------------------------------------------------------------------
extern "C" void kernel_launch(void* const* d_in, const int* in_sizes, int n_in,
                              void* d_out, int out_size)
{
    const float* x   = (const float*)d_in[0];
    const float* cs  = (const float*)d_in[1];
    const float* sn  = (const float*)d_in[2];
    const float* Wq  = (const float*)d_in[3];
    const float* Wk  = (const float*)d_in[4];
    const float* Wv  = (const float*)d_in[5];
    const float* Wo  = (const float*)d_in[6];
    float* out = (float*)d_out;

    float *qp, *kp, *vp, *yp, *xp, *wqp, *wkp, *wvp, *wop;
    cudaGetSymbolAddress((void**)&qp, g_q);
    cudaGetSymbolAddress((void**)&kp, g_k);
    cudaGetSymbolAddress((void**)&vp, g_v);
    cudaGetSymbolAddress((void**)&yp, g_y);
    cudaGetSymbolAddress((void**)&xp, g_x);
    cudaGetSymbolAddress((void**)&wqp, g_wq);
    cudaGetSymbolAddress((void**)&wkp, g_wk);
    cudaGetSymbolAddress((void**)&wvp, g_wv);
    cudaGetSymbolAddress((void**)&wop, g_wo);

    const int gemm_smem = GEMM_SM_FLOATS * 4;   // 110592 B
    cudaFuncSetAttribute(gemm_qkv, cudaFuncAttributeMaxDynamicSharedMemorySize, gemm_smem);
    cudaFuncSetAttribute(gemm_out, cudaFuncAttributeMaxDynamicSharedMemorySize, gemm_smem);
    const int fa_smem = FA_SMEM_FLOATS * 4;     // 204800 B
    cudaFuncSetAttribute(flash_attn_tf32, cudaFuncAttributeMaxDynamicSharedMemorySize, fa_smem);

    dim3 blk256(256);
    {
        int n4 = (M_ * C_) / 4;
        tf32_round_kernel<<<(n4 + 255) / 256, blk256>>>((const float4*)x, (float4*)xp, n4);
        tf32_round_T_kernel<<<dim3(C_ / 32, C_ / 32), blk256>>>(Wq, wqp, C_, C_);
        tf32_round_T_kernel<<<dim3(KVC_ / 32, C_ / 32), blk256>>>(Wk, wkp, C_, KVC_);
        tf32_round_T_kernel<<<dim3(KVC_ / 32, C_ / 32), blk256>>>(Wv, wvp, C_, KVC_);
        tf32_round_T_kernel<<<dim3(C_ / 32, C_ / 32), blk256>>>(Wo, wop, C_, C_);
    }
    gemm_qkv<<<dim3(24, M_ / 128), blk256, gemm_smem>>>(xp, wqp, wkp, wvp, cs, sn, qp, kp, vp);
    flash_attn_tf32<<<dim3(T_ / FA_BR, B_ * H_), blk256, fa_smem>>>(qp, kp, vp, yp);
    gemm_out<<<dim3(C_ / 128, M_ / 128), blk256, gemm_smem>>>(yp, wop, out);
}